// round 7
// baseline (speedup 1.0000x reference)
#include <cuda_runtime.h>
#include <cuda_fp16.h>
#include <math.h>

// Problem constants
#define B_      256
#define U_      512
#define T_STEPS 256
#define NTn     8       // n tiles (512 / 64)
#define N_TILE  64
#define NCOMP   128     // compute CTAs (16 m-groups x 8 n-tiles)
#define NRED    8       // reducer CTAs
#define WT_STRIDE 1032  // padded row stride (halfs): 2064B rows -> conflict-free LDSM
#define ZDEPTH  8

// Packed hidden-state storage:
// slab(par, col) = [m=16 rowgroups(16 rows)][kk=32][j=4][lane=32] u32 (half2)
__device__ unsigned int g_statesP[2 * 16 * 16 * 32 * 4 * 32];
// logit partials: [ZDEPTH][NTn][4 warps][B] float2
__device__ float2 g_zpart[ZDEPTH * NTn * 4 * B_];
// per-CTA completed-step counters (8 per m-group), reducer flags, z counters
__device__ int g_flags[NCOMP];
__device__ int g_rflags[NRED];
__device__ int g_zcnt[NCOMP];

// ---- smem layout offsets (bytes) ----
#define SM_WT    0                       // 64 x 1032 halves = 132096 B
#define SM_SA    132096                  // cv-stage 16KB + fresh 16KB
#define SM_SMALL (SM_SA + 32768)         // 448 floats = 1792 B
#define SM_SX    (SM_SMALL + 1792)       // 8192 B
#define SM_BAR   (SM_SX + 8192)          // mbarrier (8B, padded 16)
#define SM_TOTAL (SM_BAR + 16)

__device__ __forceinline__ int ld_acquire(const int* p) {
    int v;
    asm volatile("ld.global.acquire.gpu.b32 %0, [%1];" : "=r"(v) : "l"(p) : "memory");
    return v;
}
__device__ __forceinline__ void st_release(int* p, int v) {
    asm volatile("st.global.release.gpu.b32 [%0], %1;" :: "l"(p), "r"(v) : "memory");
}
__device__ __forceinline__ void red_release_add(int* p, int v) {
    asm volatile("red.release.gpu.global.add.s32 [%0], %1;" :: "l"(p), "r"(v) : "memory");
}
__device__ __forceinline__ float2 ldg_cg_f2(const float2* p) {
    float2 v;
    asm volatile("ld.global.cg.v2.f32 {%0,%1}, [%2];" : "=f"(v.x), "=f"(v.y) : "l"(p));
    return v;
}
__device__ __forceinline__ void cp_async16(unsigned smem_addr, const void* gptr) {
    asm volatile("cp.async.cg.shared.global [%0], [%1], 16;"
                 :: "r"(smem_addr), "l"(gptr));
}
__device__ __forceinline__ void cp_commit() {
    asm volatile("cp.async.commit_group;");
}
template <int N>
__device__ __forceinline__ void cp_wait() {
    asm volatile("cp.async.wait_group %0;" :: "n"(N) : "memory");
}
// NOTE: .noinc — counts against the init arrival count (default form would
// increment the expected count and never flip the phase -> deadlock).
__device__ __forceinline__ void cp_async_mbar_arrive_noinc(unsigned bar) {
    asm volatile("cp.async.mbarrier.arrive.noinc.shared::cta.b64 [%0];" :: "r"(bar) : "memory");
}
__device__ __forceinline__ void mbar_init(unsigned bar, unsigned cnt) {
    asm volatile("mbarrier.init.shared.b64 [%0], %1;" :: "r"(bar), "r"(cnt) : "memory");
}
__device__ __forceinline__ void mbar_wait(unsigned bar, unsigned parity) {
    unsigned done;
    asm volatile(
        "{\n\t.reg .pred p;\n\t"
        "mbarrier.try_wait.parity.acquire.cta.shared::cta.b64 p, [%1], %2;\n\t"
        "selp.b32 %0, 1, 0, p;\n\t}"
        : "=r"(done) : "r"(bar), "r"(parity) : "memory");
    while (!done) {
        asm volatile(
            "{\n\t.reg .pred p;\n\t"
            "mbarrier.try_wait.parity.acquire.cta.shared::cta.b64 p, [%1], %2, 0x989680;\n\t"
            "selp.b32 %0, 1, 0, p;\n\t}"
            : "=r"(done) : "r"(bar), "r"(parity) : "memory");
    }
}

__device__ __forceinline__ void mma16816(float acc[4],
    unsigned a0, unsigned a1, unsigned a2, unsigned a3,
    unsigned b0, unsigned b1)
{
    asm volatile(
        "mma.sync.aligned.m16n8k16.row.col.f32.f16.f16.f32 "
        "{%0,%1,%2,%3}, {%4,%5,%6,%7}, {%8,%9}, {%0,%1,%2,%3};"
        : "+f"(acc[0]), "+f"(acc[1]), "+f"(acc[2]), "+f"(acc[3])
        : "r"(a0), "r"(a1), "r"(a2), "r"(a3), "r"(b0), "r"(b1));
}

__device__ __forceinline__ unsigned* pslab(int par, int col) {
    return g_statesP + (((par << 4) + col) << 16);   // 65536 u32 per slab
}

// K=512 half-GEMM, A (16x512) + B (64-col weight slice) via ldmatrix.x4.
__device__ __forceinline__ void gemm_ldsm(unsigned aB, unsigned bB, float acc[2][4]) {
#pragma unroll 8
    for (int kk = 0; kk < 32; ++kk) {
        unsigned a0, a1, a2, a3, b0, b1, b2, b3;
        asm volatile("ldmatrix.sync.aligned.m8n8.x4.shared.b16 {%0,%1,%2,%3}, [%4];"
            : "=r"(a0), "=r"(a1), "=r"(a2), "=r"(a3) : "r"(aB));
        asm volatile("ldmatrix.sync.aligned.m8n8.x4.shared.b16 {%0,%1,%2,%3}, [%4];"
            : "=r"(b0), "=r"(b1), "=r"(b2), "=r"(b3) : "r"(bB));
        mma16816(acc[0], a0, a1, a2, a3, b0, b1);
        mma16816(acc[1], a0, a1, a2, a3, b2, b3);
        aB += 512;   // next k-chunk of A
        bB += 32;    // 16 halves forward in K
    }
}

__device__ __forceinline__ float elu1(float v) {
    return v > 0.f ? v : (__expf(v) - 1.f);
}
__device__ __forceinline__ unsigned packh2(float a, float b) {
    __half2 h = __floats2half2_rn(a, b);
    return *reinterpret_cast<unsigned*>(&h);
}

__global__ void rnn2d_init_kernel() {
    if (threadIdx.x < NCOMP) { g_flags[threadIdx.x] = 0; g_zcnt[threadIdx.x] = 0; }
    if (threadIdx.x < NRED)  g_rflags[threadIdx.x] = 0;
}

__global__ void __launch_bounds__(128) rnn2d_main_kernel(
    const int* __restrict__ x,
    const float* __restrict__ Wih, const float* __restrict__ Wiv,
    const float* __restrict__ Wch, const float* __restrict__ bch,
    const float* __restrict__ Wcv, const float* __restrict__ Wout,
    const float* __restrict__ bout, float* __restrict__ out)
{
    extern __shared__ unsigned char smem[];
    __half*   Wt = (__half*)(smem + SM_WT);              // [64][WT_STRIDE]
    unsigned* sA = (unsigned*)(smem + SM_SA);            // cv-stage + fresh
    float* sWih = (float*)(smem + SM_SMALL);             // [2][64]
    float* sWiv = sWih + 128;                            // [2][64]
    float* sBch = sWiv + 128;                            // [64]
    float* sWo0 = sBch + 64;                             // [64]
    float* sWo1 = sWo0 + 64;                             // [64]
    unsigned char* sx = (unsigned char*)(smem + SM_SX);

    const int bx  = blockIdx.x;
    const int tid = threadIdx.x;

    if (bx >= NCOMP) {
        // ---------------- reducer CTA (off the critical path) ----------------
        const int mr = bx - NCOMP;                 // handles rows 32*mr..32*mr+31
        for (int i = tid; i < 8192; i += 128) {
            int rl = i & 31, cell = i >> 5;
            sx[cell * 32 + rl] = (unsigned char)x[(32 * mr + rl) * 256 + cell];
        }
        __syncthreads();
        if (tid >= 32) return;

        const int lane = tid;
        const int b = 32 * mr + lane;
        const float bo0 = bout[0], bo1 = bout[1];
        int* myz = g_zcnt + 16 * mr;               // 16 CTAs feed these rows
        float lp = 0.f;
        for (int t = 1; t <= T_STEPS; ++t) {
            if (lane < 16) {
                while (ld_acquire(myz + lane) < 4 * t) { }
            }
            __syncwarp();
            asm volatile("membar.gl;" ::: "memory");
            float z0 = bo0, z1 = bo1;
            const float2* zp = g_zpart + (t & (ZDEPTH - 1)) * (NTn * 4 * B_) + b;
#pragma unroll
            for (int i = 0; i < 32; ++i) {
                float2 v = ldg_cg_f2(zp + i * B_);
                z0 += v.x; z1 += v.y;
            }
            int s = t - 1, r = s >> 4, p = s & 15;
            int c = (r & 1) ? (15 - p) : p;
            int spin = sx[(r * 16 + c) * 32 + lane];
            float mz = fmaxf(z0, z1);
            float lse = mz + logf(expf(z0 - mz) + expf(z1 - mz));
            lp += (spin ? z1 : z0) - lse;
            __syncwarp();
            if (lane == 0) st_release(&g_rflags[mr], t);
        }
        out[b] = lp;
        return;
    }

    // ---------------- compute CTA ----------------
    const int m = bx >> 3, n = bx & 7;           // 16-row group, 64-col tile
    const int w = tid >> 5, lane = tid & 31;     // warp w handles cols 16w..16w+15
    const int n0 = n * N_TILE;
    const int q = lane >> 2, tg = lane & 3;

    const unsigned sA_s = (unsigned)__cvta_generic_to_shared(sA);
    const unsigned wt_s = (unsigned)__cvta_generic_to_shared(Wt);
    const unsigned hbar = (unsigned)__cvta_generic_to_shared(smem + SM_BAR);
    const unsigned aOff = ((lane >> 3) << 7) + ((lane & 7) << 4);      // A tile addr
    const unsigned brow = 16 * w + 8 * (lane >> 4) + (lane & 7);       // B tile row
    const unsigned bOff = wt_s + brow * (WT_STRIDE * 2) + (((lane >> 3) & 1) << 4);

    // ---- resident weight slice: Wt[j][k] = W[k][n0+j]
    for (int i = tid; i < N_TILE * 1024; i += 128) {
        int j = i >> 10, k = i & 1023;
        float wv = (k < U_) ? Wch[k * U_ + n0 + j] : Wcv[(k - U_) * U_ + n0 + j];
        Wt[j * WT_STRIDE + k] = __float2half_rn(wv);
    }
    if (tid < 64) {
        sWih[tid]       = Wih[n0 + tid];
        sWih[64 + tid]  = Wih[U_ + n0 + tid];
        sWiv[tid]       = Wiv[n0 + tid];
        sWiv[64 + tid]  = Wiv[U_ + n0 + tid];
        sBch[tid]       = bch[n0 + tid];
        sWo0[tid]       = Wout[(n0 + tid) * 2 + 0];
        sWo1[tid]       = Wout[(n0 + tid) * 2 + 1];
    }
    for (int i = tid; i < 4096; i += 128) {      // spins for this CTA's 16 rows
        int rl = i & 15, cell = i >> 4;
        sx[cell * 16 + rl] = (unsigned char)x[(16 * m + rl) * 256 + cell];
    }
    if (tid == 0) mbar_init(hbar, 32);
    __syncthreads();

    int* myflags = g_flags + m * 8;

#pragma unroll 1
    for (int t = 1; t <= T_STEPS; ++t) {
        const int s = t - 1;
        const int r = s >> 4, p = s & 15;
        const int c  = (r & 1) ? (15 - p) : p;
        const int cp = (r & 1) ? (c + 1) : (c - 1);
        const bool has_h = (p > 0), has_v = (r > 0);

        // (a) own cv-prefetch (issued end of prev step) complete + CTA-wide visible
        cp_wait<0>();
        __syncthreads();

        // warp 0: detect deps, pull the fresh tile, signal via mbarrier
        if (w == 0 && t > 1) {
            if (lane < 8) {
                while (ld_acquire(myflags + lane) < t - 1) { }
            }
            if (lane == 8 && t > ZDEPTH) {
                while (ld_acquire(&g_rflags[m >> 1]) < t - ZDEPTH) { }
            }
            __syncwarp();
            const unsigned* fsrc = has_h ? (pslab(r & 1, cp) + (m << 12))
                                         : (pslab((r - 1) & 1, c) + (m << 12));
            const unsigned dstb = sA_s + 16384;
#pragma unroll
            for (int i = 0; i < 32; ++i)
                cp_async16(dstb + lane * 16 + i * 512, fsrc + lane * 4 + i * 128);
            cp_async_mbar_arrive_noinc(hbar);
        }

        float acc[2][4];
#pragma unroll
        for (int f = 0; f < 2; ++f)
            acc[f][0] = acc[f][1] = acc[f][2] = acc[f][3] = 0.f;

        // old-cv GEMM runs concurrently with warp0's poll + fresh copy
        if (has_v && has_h)
            gemm_ldsm(sA_s + aOff, bOff + 1024, acc);

        if (t > 1) {
            mbar_wait(hbar, t & 1);
            gemm_ldsm(sA_s + 16384 + aOff, has_h ? bOff : bOff + 1024, acc);
        }

        // ---- epilogue: v values + Pout stores (peer-critical), z FMAs in regs
        int sLa = 0, sLb = 0, sUa = 0, sUb = 0;
        if (has_h) {
            sLa = sx[(r * 16 + cp) * 16 + q];
            sLb = sx[(r * 16 + cp) * 16 + q + 8];
        }
        if (has_v) {
            sUa = sx[((r - 1) * 16 + c) * 16 + q];
            sUb = sx[((r - 1) * 16 + c) * 16 + q + 8];
        }

        float z0a = 0.f, z1a = 0.f, z0b = 0.f, z1b = 0.f;
        unsigned* Pout = pslab(r & 1, c) + (m << 12) + ((4 * n + w) << 7) + lane;
#pragma unroll
        for (int f = 0; f < 2; ++f) {
            int u0 = 16 * w + 8 * f + 2 * tg;
            float v0 = acc[f][0] + sBch[u0];
            float v1 = acc[f][1] + sBch[u0 + 1];
            float v2 = acc[f][2] + sBch[u0];
            float v3 = acc[f][3] + sBch[u0 + 1];
            if (has_h) {
                v0 += sWih[sLa * 64 + u0]; v1 += sWih[sLa * 64 + u0 + 1];
                v2 += sWih[sLb * 64 + u0]; v3 += sWih[sLb * 64 + u0 + 1];
            }
            if (has_v) {
                v0 += sWiv[sUa * 64 + u0]; v1 += sWiv[sUa * 64 + u0 + 1];
                v2 += sWiv[sUb * 64 + u0]; v3 += sWiv[sUb * 64 + u0 + 1];
            }
            v0 = elu1(v0); v1 = elu1(v1); v2 = elu1(v2); v3 = elu1(v3);

            z0a += v0 * sWo0[u0] + v1 * sWo0[u0 + 1];
            z1a += v0 * sWo1[u0] + v1 * sWo1[u0 + 1];
            z0b += v2 * sWo0[u0] + v3 * sWo0[u0 + 1];
            z1b += v2 * sWo1[u0] + v3 * sWo1[u0 + 1];

            Pout[(2 * f) * 32]     = packh2(v0, v1);
            Pout[(2 * f + 1) * 32] = packh2(v2, v3);
        }

        // (b) peer-visible release ASAP: only Pout stores gate the neighbors
        __syncthreads();
        if (tid == 0) st_release(&g_flags[bx], t);

        // ---- z tail (reducer-only consumers), off the peer critical path
        z0a += __shfl_xor_sync(0xffffffffu, z0a, 1);
        z0a += __shfl_xor_sync(0xffffffffu, z0a, 2);
        z1a += __shfl_xor_sync(0xffffffffu, z1a, 1);
        z1a += __shfl_xor_sync(0xffffffffu, z1a, 2);
        z0b += __shfl_xor_sync(0xffffffffu, z0b, 1);
        z0b += __shfl_xor_sync(0xffffffffu, z0b, 2);
        z1b += __shfl_xor_sync(0xffffffffu, z1b, 1);
        z1b += __shfl_xor_sync(0xffffffffu, z1b, 2);
        if (tg == 0) {
            float2* zp = g_zpart + (((t & (ZDEPTH - 1)) * NTn + n) * 4 + w) * B_;
            int bA = 16 * m + q;
            zp[bA]     = make_float2(z0a, z1a);
            zp[bA + 8] = make_float2(z0b, z1b);
        }
        __syncwarp();
        if (lane == 0) red_release_add(&g_zcnt[bx], 1);

        // ---- prefetch old-cv for step t+1 (dep <= t-2, ordering via (b)+acquires)
        if (t < T_STEPS) {
            int r2 = t >> 4, p2 = t & 15;
            if (p2 >= 1 && r2 >= 1) {
                int c2 = (r2 & 1) ? (15 - p2) : p2;
                const unsigned* src = pslab((r2 - 1) & 1, c2) + (m << 12);
#pragma unroll
                for (int i = 0; i < 8; ++i)
                    cp_async16(sA_s + tid * 16 + i * 2048, src + tid * 4 + i * 512);
            }
            cp_commit();
        }
    }
}

extern "C" void kernel_launch(void* const* d_in, const int* in_sizes, int n_in,
                              void* d_out, int out_size)
{
    (void)in_sizes; (void)n_in; (void)out_size;
    const int*   x    = (const int*)  d_in[0];
    const float* Wih  = (const float*)d_in[1];
    const float* Wiv  = (const float*)d_in[2];
    const float* Wch  = (const float*)d_in[3];
    const float* bch  = (const float*)d_in[4];
    const float* Wcv  = (const float*)d_in[5];
    const float* Wout = (const float*)d_in[6];
    const float* bout = (const float*)d_in[7];
    float* out = (float*)d_out;

    cudaFuncSetAttribute(rnn2d_main_kernel,
                         cudaFuncAttributeMaxDynamicSharedMemorySize, SM_TOTAL);

    rnn2d_init_kernel<<<1, 128>>>();
    rnn2d_main_kernel<<<NCOMP + NRED, 128, SM_TOTAL>>>(
        x, Wih, Wiv, Wch, bch, Wcv, Wout, bout, out);
}